// round 2
// baseline (speedup 1.0000x reference)
#include <cuda_runtime.h>
#include <math.h>

// Problem constants
#define CC      512
#define BB      16
#define TT      60
#define NP      196
#define NHEADS  4
#define HD      128
#define CLIPL   6
#define NFRAMES 36
#define TOPK    6
#define TOPM    12

// Output layout (concatenated flat, float32):
//   [0]                audio_top_k        (16,36,512)      = 294912
//   [294912]           visual_patch_top_m (16,36,12,512)   = 3538944
//   [3833856]          visual_patch_feat  (16,432,512)     = 3538944  (same bytes)
#define OFF1 294912
#define OFF2 3833856

// Scratch (device globals — no allocation allowed)
__device__ float g_q[CC];              // q projection for batch 0
__device__ float g_r[NHEADS * CC];     // r_h[c] = sum_j Wk[h*128+j, c] * q[h*128+j]
__device__ float g_qbk[NHEADS];        // q_h . bk_h
__device__ float g_scores[NHEADS * NP];
__device__ int   g_pid;

// ---------------------------------------------------------------------------
// K1: q[row] = Wq[row,:] . qst[0,:] + bq[row]    (warp per row, 64 warps)
// ---------------------------------------------------------------------------
__global__ void k_q(const float* __restrict__ W, const float* __restrict__ bias,
                    const float* __restrict__ qst) {
    int warp = (blockIdx.x * blockDim.x + threadIdx.x) >> 5;   // 0..63
    int lane = threadIdx.x & 31;
    const float4* x4 = (const float4*)qst;  // batch 0 = first 512 floats
    #pragma unroll
    for (int rr = 0; rr < 8; rr++) {
        int row = warp * 8 + rr;
        const float4* w4 = (const float4*)(W + (size_t)row * CC);
        float acc = 0.f;
        for (int i = lane; i < CC / 4; i += 32) {
            float4 a = w4[i], b = x4[i];
            acc += a.x * b.x + a.y * b.y + a.z * b.z + a.w * b.w;
        }
        #pragma unroll
        for (int o = 16; o; o >>= 1) acc += __shfl_down_sync(0xffffffffu, acc, o);
        if (lane == 0) g_q[row] = acc + bias[row];
    }
}

// ---------------------------------------------------------------------------
// K2: r[h*512+c] = sum_{j<128} Wk[h*128+j, c] * q[h*128+j]   (thread per (h,c))
//     also g_qbk[h] = q_h . bk_h
// ---------------------------------------------------------------------------
__global__ void k_r(const float* __restrict__ W, const float* __restrict__ bias) {
    int idx = blockIdx.x * blockDim.x + threadIdx.x;   // 0..2047
    int h = idx >> 9, c = idx & 511;
    const float* wcol = W + ((size_t)(CC + h * HD)) * CC + c;  // Wk rows start at 512
    float acc = 0.f;
    #pragma unroll 8
    for (int j = 0; j < HD; j++) acc += wcol[(size_t)j * CC] * g_q[h * HD + j];
    g_r[idx] = acc;
    if (idx < NHEADS) {
        float s = 0.f;
        for (int j = 0; j < HD; j++) s += g_q[idx * HD + j] * bias[CC + idx * HD + j];
        g_qbk[idx] = s;
    }
}

// ---------------------------------------------------------------------------
// K3: per-patch scores at (b=0, f=0).  Block per patch n (196 blocks, 128 thr)
//     score[h][n] = scale * (r_h . x_n + q_h.bk_h)
// ---------------------------------------------------------------------------
__global__ void k_scores(const float* __restrict__ patch, const int* __restrict__ topk) {
    int n = blockIdx.x;
    int t = threadIdx.x;            // 128 threads
    int f0 = topk[0] * CLIPL;       // frame_ids[0,0] = seg_idx[0,0]*CLIP + 0
    const float* x = patch + (((size_t)f0 * NP) + n) * CC;   // batch 0
    float xv[4];
    #pragma unroll
    for (int i = 0; i < 4; i++) xv[i] = x[t + i * 128];
    float acc[4] = {0.f, 0.f, 0.f, 0.f};
    #pragma unroll
    for (int h = 0; h < 4; h++)
        #pragma unroll
        for (int i = 0; i < 4; i++)
            acc[h] += g_r[h * CC + t + i * 128] * xv[i];

    __shared__ float red[4][128];
    #pragma unroll
    for (int h = 0; h < 4; h++) red[h][t] = acc[h];
    __syncthreads();
    int w = t >> 5, lane = t & 31;
    float v = red[w][lane] + red[w][lane + 32] + red[w][lane + 64] + red[w][lane + 96];
    #pragma unroll
    for (int o = 16; o; o >>= 1) v += __shfl_down_sync(0xffffffffu, v, o);
    if (lane == 0)
        g_scores[w * NP + n] = 0.08838834764831845f * (v + g_qbk[w]);  // 1/sqrt(128)
}

// ---------------------------------------------------------------------------
// K4: softmax per head over 196, mean over heads, select pid
//     pid = max n such that n is among the 12 largest w[n]
//     (stable-argsort tie-break: strictly greater OR equal with larger index)
// ---------------------------------------------------------------------------
__global__ void k_pid() {
    __shared__ float w[NP];
    __shared__ float mx[NHEADS], inv[NHEADS];
    __shared__ int spid;
    int t = threadIdx.x;            // 256 threads
    int warp = t >> 5, lane = t & 31;
    if (warp < NHEADS) {
        float m = -1e30f;
        for (int n = lane; n < NP; n += 32) m = fmaxf(m, g_scores[warp * NP + n]);
        #pragma unroll
        for (int o = 16; o; o >>= 1) m = fmaxf(m, __shfl_xor_sync(0xffffffffu, m, o));
        float s = 0.f;
        for (int n = lane; n < NP; n += 32) s += expf(g_scores[warp * NP + n] - m);
        #pragma unroll
        for (int o = 16; o; o >>= 1) s += __shfl_xor_sync(0xffffffffu, s, o);
        if (lane == 0) { mx[warp] = m; inv[warp] = 1.f / s; }
    }
    if (t == 0) spid = -1;
    __syncthreads();
    if (t < NP) {
        float acc = 0.f;
        #pragma unroll
        for (int h = 0; h < NHEADS; h++)
            acc += expf(g_scores[h * NP + t] - mx[h]) * inv[h];
        w[t] = acc * 0.25f;
    }
    __syncthreads();
    if (t < NP) {
        float wn = w[t];
        int cnt = 0;
        for (int m = 0; m < NP; m++)
            cnt += (w[m] > wn) || (w[m] == wn && m > t);
        if (cnt < TOPM) atomicMax(&spid, t);
    }
    __syncthreads();
    if (t == 0) g_pid = spid;
}

// ---------------------------------------------------------------------------
// K5: gathers + broadcast writes.  Block per (b,f) pair (576 blocks, 128 thr)
// ---------------------------------------------------------------------------
__global__ void k_gather(const float* __restrict__ audio,
                         const float* __restrict__ patch,
                         const int* __restrict__ topk,
                         float* __restrict__ out) {
    int bf = blockIdx.x;            // 0..575
    int t  = threadIdx.x;           // 0..127 (float4 lanes over C=512)
    int b = bf / NFRAMES, f = bf % NFRAMES;
    int seg   = topk[b * TOPK + f / CLIPL];
    int frame = seg * CLIPL + (f % CLIPL);

    const float4* a4 = (const float4*)audio;
    const float4* p4 = (const float4*)patch;
    float4*       o4 = (float4*)out;

    // audio_top_k[b,f,:]
    float4 a = a4[((size_t)b * TT + frame) * 128 + t];
    o4[(size_t)bf * 128 + t] = a;

    // visual_patch_top_m / visual_patch_feat: broadcast of patch row pid
    int pid = g_pid;
    float4 p = p4[(((size_t)b * TT + frame) * NP + pid) * 128 + t];
    size_t base1 = OFF1 / 4 + (size_t)bf * TOPM * 128 + t;
    size_t base2 = OFF2 / 4 + (size_t)bf * TOPM * 128 + t;
    #pragma unroll
    for (int m = 0; m < TOPM; m++) {
        o4[base1 + (size_t)m * 128] = p;
        o4[base2 + (size_t)m * 128] = p;
    }
}

// ---------------------------------------------------------------------------
extern "C" void kernel_launch(void* const* d_in, const int* in_sizes, int n_in,
                              void* d_out, int out_size) {
    const float* audio   = (const float*)d_in[0];   // (16,60,512)
    const float* patch   = (const float*)d_in[1];   // (16,60,196,512)
    const float* qst     = (const float*)d_in[2];   // (16,512)
    const int*   topk    = (const int*)  d_in[3];   // (16,1,6) int32
    const float* in_w    = (const float*)d_in[4];   // (1536,512)
    const float* in_b    = (const float*)d_in[5];   // (1536,)
    float* out = (float*)d_out;

    k_q<<<16, 128>>>(in_w, in_b, qst);
    k_r<<<8, 256>>>(in_w, in_b);
    k_scores<<<NP, 128>>>(patch, topk);
    k_pid<<<1, 256>>>();
    k_gather<<<BB * NFRAMES, 128>>>(audio, patch, topk, out);
}